// round 3
// baseline (speedup 1.0000x reference)
#include <cuda_runtime.h>
#include <math.h>

#define BB 2048
#define LL 1024
#define HH 64
#define VV 64

// ---------------- precomputed tables (device globals; no allocation) ----------------
__device__ float d_G[HH * HH];     // Gram matrix G = K K^T (symmetric)
__device__ float d_Z[HH * HH];     // Z = K @ read_w @ out_w   (row-major [i][n])
__device__ float d_a[HH];          // a_v = g_v / (G[v][v] + 1e-6)
__device__ float d_r[HH];          // r_v = g_v / a_v
__device__ float d_bias2[HH];      // read_b @ out_w + out_b

// ---------------- precompute: 64 tokens -> k table, gram, gates, output fold ----------------
__global__ void precompute_kernel(
    const float* __restrict__ embed_W, const float* __restrict__ ff_w1, const float* __restrict__ ff_b1,
    const float* __restrict__ ff_w2,   const float* __restrict__ ff_b2, const float* __restrict__ ln_g,
    const float* __restrict__ ln_b,    const float* __restrict__ gate_w1, const float* __restrict__ gate_b1,
    const float* __restrict__ gate_w2, const float* __restrict__ gate_b2, const float* __restrict__ read_w,
    const float* __restrict__ read_b,  const float* __restrict__ out_w,   const float* __restrict__ out_b)
{
    __shared__ float sK[HH][HH];
    __shared__ float sY[HH][HH];
    int v = threadIdx.x;
    if (v >= HH) return;

    // embedding row for token v
    float e[HH];
    #pragma unroll 1
    for (int i = 0; i < HH; i++) e[i] = embed_W[v * HH + i];

    // ff = relu(e @ ff_w1 + b1) @ ff_w2 + b2
    float ff[HH];
    #pragma unroll 1
    for (int i = 0; i < HH; i++) ff[i] = ff_b2[i];
    #pragma unroll 1
    for (int j = 0; j < 2 * HH; j++) {
        float z = ff_b1[j];
        #pragma unroll 1
        for (int i = 0; i < HH; i++) z += e[i] * ff_w1[i * (2 * HH) + j];
        if (z > 0.0f) {
            #pragma unroll 1
            for (int i = 0; i < HH; i++) ff[i] += z * ff_w2[j * HH + i];
        }
    }

    // layernorm(e + ff)
    float x[HH];
    float mu = 0.0f;
    #pragma unroll 1
    for (int i = 0; i < HH; i++) { x[i] = e[i] + ff[i]; mu += x[i]; }
    mu *= (1.0f / HH);
    float var = 0.0f;
    #pragma unroll 1
    for (int i = 0; i < HH; i++) { float d = x[i] - mu; var += d * d; }
    var *= (1.0f / HH);
    float inv = rsqrtf(var + 1e-5f);
    #pragma unroll 1
    for (int i = 0; i < HH; i++) {
        sK[v][i] = (x[i] - mu) * inv * ln_g[i] + ln_b[i];
    }

    // gate scalar g_v = sigmoid(relu(k @ gw1 + gb1) @ gw2 + gb2)
    float gz = gate_b2[0];
    #pragma unroll 1
    for (int j = 0; j < 16; j++) {
        float hj = gate_b1[j];
        #pragma unroll 1
        for (int i = 0; i < HH; i++) hj += sK[v][i] * gate_w1[i * 16 + j];
        if (hj > 0.0f) gz += hj * gate_w2[j];
    }
    float g = 1.0f / (1.0f + expf(-gz));

    __syncthreads();

    // Gram row v
    float diag = 0.0f;
    #pragma unroll 1
    for (int u = 0; u < HH; u++) {
        float s = 0.0f;
        #pragma unroll 1
        for (int i = 0; i < HH; i++) s += sK[v][i] * sK[u][i];
        d_G[v * HH + u] = s;
        if (u == v) diag = s;
    }
    float denom = diag + 1e-6f;
    float a = g / denom;
    d_a[v] = a;
    d_r[v] = g / a;

    // Y = read_w @ out_w (row v)
    #pragma unroll 1
    for (int n = 0; n < HH; n++) {
        float s = 0.0f;
        #pragma unroll 1
        for (int m = 0; m < HH; m++) s += read_w[v * HH + m] * out_w[m * HH + n];
        sY[v][n] = s;
    }
    // bias2
    {
        float s = out_b[v];
        #pragma unroll 1
        for (int m = 0; m < HH; m++) s += read_b[m] * out_w[m * HH + v];
        d_bias2[v] = s;
    }
    __syncthreads();

    // Z row v = k_v @ Y
    #pragma unroll 1
    for (int n = 0; n < HH; n++) {
        float s = 0.0f;
        #pragma unroll 1
        for (int h = 0; h < HH; h++) s += sK[v][h] * sY[h][n];
        d_Z[v * HH + n] = s;
    }
}

// ---------------- packed dual-fp32 helpers ----------------
__device__ __forceinline__ unsigned long long fma_f32x2(unsigned long long a, unsigned long long b,
                                                        unsigned long long c) {
    unsigned long long d;
    asm("fma.rn.f32x2 %0, %1, %2, %3;" : "=l"(d) : "l"(a), "l"(b), "l"(c));
    return d;
}
__device__ __forceinline__ unsigned long long bcast2(float x) {
    unsigned long long r;
    unsigned int u = __float_as_uint(x);
    asm("mov.b64 %0, {%1, %2};" : "=l"(r) : "r"(u), "r"(u));
    return r;
}

// ---------------- scan: one warp per batch, P = N*G resident in registers ----------------
__global__ void __launch_bounds__(128) scan_kernel(const int* __restrict__ seq, float* __restrict__ out)
{
    __shared__ float sG[HH * HH];
    __shared__ float sa[HH];
    __shared__ float sr[HH];
    __shared__ __align__(16) float sbuf[4][2][HH];   // per-warp double-buffered staging vector

    int tid = threadIdx.x;
    #pragma unroll 1
    for (int i = tid; i < HH * HH; i += 128) sG[i] = d_G[i];
    if (tid < HH) { sa[tid] = d_a[tid]; sr[tid] = d_r[tid]; }
    __syncthreads();

    int w = tid >> 5;
    int lane = tid & 31;
    int b = blockIdx.x * 4 + w;
    const int* seqb = seq + (long)b * LL;

    // Lane j owns columns j (cA) and j+32 (cB) of P; each u64 packs rows (2i, 2i+1).
    unsigned long long cA[32], cB[32];
    #pragma unroll
    for (int i = 0; i < 32; i++) { cA[i] = 0ull; cB[i] = 0ull; }

    int tok = 0;
    #pragma unroll 1
    for (int t = 0; t < LL - 1; t++) {
        if ((t & 31) == 0) tok = seqb[t + lane];          // 1 coalesced LDG / 32 steps
        int v = __shfl_sync(0xffffffffu, tok, t & 31);

        float a  = sa[v];
        float c1 = -a * sG[v * HH + lane];
        float c2 = -a * sG[v * HH + 32 + lane];

        float* sb = sbuf[w][t & 1];
        if (lane == (v & 31)) {
            // owner dumps its column (= w = P[:,v]) to smem
            if (v & 32) {
                #pragma unroll
                for (int p = 0; p < 32; p += 2) {
                    ulonglong2 t2; t2.x = cB[p]; t2.y = cB[p + 1];
                    *reinterpret_cast<ulonglong2*>(sb + 2 * p) = t2;
                }
            } else {
                #pragma unroll
                for (int p = 0; p < 32; p += 2) {
                    ulonglong2 t2; t2.x = cA[p]; t2.y = cA[p + 1];
                    *reinterpret_cast<ulonglong2*>(sb + 2 * p) = t2;
                }
            }
            sb[v] -= sr[v];     // s = w - (g/a) e_v, so  dP[:,j] = (-a*G[v][j]) * s
        }
        __syncwarp();

        unsigned long long cp1 = bcast2(c1);
        unsigned long long cp2 = bcast2(c2);
        const ulonglong2* s2 = reinterpret_cast<const ulonglong2*>(sb);
        #pragma unroll
        for (int p = 0; p < 16; p++) {
            ulonglong2 sv = s2[p];
            cA[2 * p]     = fma_f32x2(cp1, sv.x, cA[2 * p]);
            cA[2 * p + 1] = fma_f32x2(cp1, sv.y, cA[2 * p + 1]);
            cB[2 * p]     = fma_f32x2(cp2, sv.x, cB[2 * p]);
            cB[2 * p + 1] = fma_f32x2(cp2, sv.y, cB[2 * p + 1]);
        }
    }

    // ---- final readout: logits = P[:,v_q]^T Z + bias2 ----
    int vq = seqb[LL - 1];
    float* sb = sbuf[w][1];     // step 1022 used buffer 0; buffer 1 is safe to overwrite
    if (lane == (vq & 31)) {
        if (vq & 32) {
            #pragma unroll
            for (int p = 0; p < 32; p += 2) {
                ulonglong2 t2; t2.x = cB[p]; t2.y = cB[p + 1];
                *reinterpret_cast<ulonglong2*>(sb + 2 * p) = t2;
            }
        } else {
            #pragma unroll
            for (int p = 0; p < 32; p += 2) {
                ulonglong2 t2; t2.x = cA[p]; t2.y = cA[p + 1];
                *reinterpret_cast<ulonglong2*>(sb + 2 * p) = t2;
            }
        }
    }
    __syncwarp();

    float acc1 = d_bias2[lane];
    float acc2 = d_bias2[lane + 32];
    #pragma unroll
    for (int i = 0; i < HH; i++) {
        float pi = sb[i];
        acc1 += pi * d_Z[i * HH + lane];
        acc2 += pi * d_Z[i * HH + 32 + lane];
    }
    out[(long)b * HH + lane]      = acc1;
    out[(long)b * HH + 32 + lane] = acc2;
}

// ---------------- launch ----------------
extern "C" void kernel_launch(void* const* d_in, const int* in_sizes, int n_in,
                              void* d_out, int out_size)
{
    const int*   seq     = (const int*)  d_in[0];
    const float* embed_W = (const float*)d_in[1];
    const float* ff_w1   = (const float*)d_in[2];
    const float* ff_b1   = (const float*)d_in[3];
    const float* ff_w2   = (const float*)d_in[4];
    const float* ff_b2   = (const float*)d_in[5];
    const float* ln_g    = (const float*)d_in[6];
    const float* ln_b    = (const float*)d_in[7];
    const float* gate_w1 = (const float*)d_in[8];
    const float* gate_b1 = (const float*)d_in[9];
    const float* gate_w2 = (const float*)d_in[10];
    const float* gate_b2 = (const float*)d_in[11];
    const float* read_w  = (const float*)d_in[12];
    const float* read_b  = (const float*)d_in[13];
    const float* out_w   = (const float*)d_in[14];
    const float* out_b   = (const float*)d_in[15];

    precompute_kernel<<<1, 64>>>(embed_W, ff_w1, ff_b1, ff_w2, ff_b2, ln_g, ln_b,
                                 gate_w1, gate_b1, gate_w2, gate_b2,
                                 read_w, read_b, out_w, out_b);
    scan_kernel<<<BB / 4, 128>>>(seq, (float*)d_out);
}

// round 4
// speedup vs baseline: 5.0645x; 5.0645x over previous
#include <cuda_runtime.h>
#include <math.h>

#define BB 2048
#define LL 1024
#define HH 64
#define VV 64

// ---------------- precomputed tables (device globals; no allocation) ----------------
__device__ float d_K[HH * HH];     // per-token key vectors k_v (row v)
__device__ float d_g[HH];          // gate scalar per token
__device__ float d_Gn[HH * HH];    // Gn[v][j] = -a_v * (k_v . k_j)   (a folded in)
__device__ float d_r[HH];          // r_v = ||k_v||^2 + 1e-6  (= g/a)
__device__ float d_Y[HH * HH];     // Y = read_w @ out_w
__device__ float d_Z[HH * HH];     // Z = K @ Y
__device__ float d_bias2[HH];      // read_b @ out_w + out_b

// ---------------- precompute A: token table (block per token, thread per feature) ----------------
__global__ void __launch_bounds__(128) prekA(
    const float* __restrict__ embed_W, const float* __restrict__ ff_w1, const float* __restrict__ ff_b1,
    const float* __restrict__ ff_w2,   const float* __restrict__ ff_b2, const float* __restrict__ ln_g,
    const float* __restrict__ ln_b,    const float* __restrict__ gate_w1, const float* __restrict__ gate_b1,
    const float* __restrict__ gate_w2, const float* __restrict__ gate_b2)
{
    int v = blockIdx.x;
    int tid = threadIdx.x;
    __shared__ float se[HH];
    __shared__ float sz[2 * HH];
    __shared__ float sk[HH];
    __shared__ float sh[16];
    __shared__ float sred[4];

    if (tid < HH) se[tid] = embed_W[v * HH + tid];
    __syncthreads();

    // hidden layer: z_j = relu(e @ ff_w1 + b1), j = tid (128 dims)
    {
        float z = ff_b1[tid];
        #pragma unroll 8
        for (int i = 0; i < HH; i++) z = fmaf(se[i], ff_w1[i * (2 * HH) + tid], z);
        sz[tid] = fmaxf(z, 0.0f);
    }
    __syncthreads();

    // ff_i + residual + layernorm (threads 0..63, two warps)
    if (tid < HH) {
        float ff = ff_b2[tid];
        #pragma unroll 8
        for (int j = 0; j < 2 * HH; j++) ff = fmaf(sz[j], ff_w2[j * HH + tid], ff);
        float x = se[tid] + ff;

        // mean over 64 threads
        float s = x;
        #pragma unroll
        for (int o = 16; o > 0; o >>= 1) s += __shfl_xor_sync(0xffffffffu, s, o);
        if ((tid & 31) == 0) sred[tid >> 5] = s;
        __syncwarp();
        __syncthreads();
        float mu = (sred[0] + sred[1]) * (1.0f / HH);

        float d = x - mu;
        float sv = d * d;
        #pragma unroll
        for (int o = 16; o > 0; o >>= 1) sv += __shfl_xor_sync(0xffffffffu, sv, o);
        if ((tid & 31) == 0) sred[2 + (tid >> 5)] = sv;
        __syncwarp();
        __syncthreads();
        float var = (sred[2] + sred[3]) * (1.0f / HH);
        float inv = rsqrtf(var + 1e-5f);
        float k = d * inv * ln_g[tid] + ln_b[tid];
        sk[tid] = k;
        d_K[v * HH + tid] = k;
    }
    __syncthreads();

    // gate: 16 hidden, then scalar
    if (tid < 16) {
        float hj = gate_b1[tid];
        #pragma unroll 8
        for (int i = 0; i < HH; i++) hj = fmaf(sk[i], gate_w1[i * 16 + tid], hj);
        sh[tid] = fmaxf(hj, 0.0f);
    }
    __syncthreads();
    if (tid == 0) {
        float gz = gate_b2[0];
        #pragma unroll
        for (int j = 0; j < 16; j++) gz = fmaf(sh[j], gate_w2[j], gz);
        d_g[v] = 1.0f / (1.0f + expf(-gz));
    }
}

// ---------------- precompute B: Gram (with -a folded), r, Y, bias2 ----------------
__global__ void __launch_bounds__(64) prekB(
    const float* __restrict__ read_w, const float* __restrict__ read_b,
    const float* __restrict__ out_w,  const float* __restrict__ out_b)
{
    int v = blockIdx.x;
    int u = threadIdx.x;
    __shared__ float skv[HH];
    __shared__ float sdiag;

    skv[u] = d_K[v * HH + u];
    __syncthreads();

    float s = 0.0f;
    #pragma unroll 8
    for (int i = 0; i < HH; i++) s = fmaf(skv[i], d_K[u * HH + i], s);
    if (u == v) sdiag = s;
    __syncthreads();

    float denom = sdiag + 1e-6f;
    float a = d_g[v] / denom;
    d_Gn[v * HH + u] = -a * s;
    if (u == v) d_r[v] = denom;          // r = g/a = ||k||^2 + eps

    // Y row v, element u
    float y = 0.0f;
    #pragma unroll 8
    for (int m = 0; m < HH; m++) y = fmaf(read_w[v * HH + m], out_w[m * HH + u], y);
    d_Y[v * HH + u] = y;

    if (v == 0) {
        float b = out_b[u];
        #pragma unroll 8
        for (int m = 0; m < HH; m++) b = fmaf(read_b[m], out_w[m * HH + u], b);
        d_bias2[u] = b;
    }
}

// ---------------- precompute C: Z = K @ Y ----------------
__global__ void __launch_bounds__(64) prekC()
{
    int v = blockIdx.x;
    int n = threadIdx.x;
    __shared__ float skv[HH];
    skv[n] = d_K[v * HH + n];
    __syncthreads();
    float s = 0.0f;
    #pragma unroll 8
    for (int h = 0; h < HH; h++) s = fmaf(skv[h], d_Y[h * HH + n], s);
    d_Z[v * HH + n] = s;
}

// ---------------- packed dual-fp32 helpers ----------------
__device__ __forceinline__ unsigned long long fma_f32x2(unsigned long long a, unsigned long long b,
                                                        unsigned long long c) {
    unsigned long long d;
    asm("fma.rn.f32x2 %0, %1, %2, %3;" : "=l"(d) : "l"(a), "l"(b), "l"(c));
    return d;
}
__device__ __forceinline__ unsigned long long bcast2(float x) {
    unsigned long long r;
    unsigned int u = __float_as_uint(x);
    asm("mov.b64 %0, {%1, %2};" : "=l"(r) : "r"(u), "r"(u));
    return r;
}

// ---------------- scan: one warp per batch, P = N*G resident in registers ----------------
__global__ void __launch_bounds__(128) scan_kernel(const int* __restrict__ seq, float* __restrict__ out)
{
    __shared__ float sGn[HH * HH];
    __shared__ float sr[HH];
    __shared__ __align__(16) float sbuf[4][2][HH];   // per-warp double-buffered staging vector

    int tid = threadIdx.x;
    #pragma unroll 1
    for (int i = tid; i < HH * HH; i += 128) sGn[i] = d_Gn[i];
    if (tid < HH) sr[tid] = d_r[tid];
    __syncthreads();

    int w = tid >> 5;
    int lane = tid & 31;
    int b = blockIdx.x * 4 + w;
    const int* seqb = seq + (long)b * LL;

    // Lane j owns columns j (cA) and j+32 (cB) of P; each u64 packs rows (2i, 2i+1).
    unsigned long long cA[32], cB[32];
    #pragma unroll
    for (int i = 0; i < 32; i++) { cA[i] = 0ull; cB[i] = 0ull; }

    int tok = seqb[lane];
    int v0 = __shfl_sync(0xffffffffu, tok, 0);
    float c1 = sGn[v0 * HH + lane];
    float c2 = sGn[v0 * HH + 32 + lane];
    int v = v0;

    #pragma unroll 1
    for (int t = 0; t < LL - 1; t++) {
        // prefetch next step's token + coefficients (independent of this step's update)
        int tn = t + 1;
        if ((tn & 31) == 0 && tn < LL) tok = seqb[tn + lane];
        int vn = __shfl_sync(0xffffffffu, tok, tn & 31);
        float c1n = sGn[vn * HH + lane];
        float c2n = sGn[vn * HH + 32 + lane];

        float* sb = sbuf[w][t & 1];
        if (lane == (v & 31)) {
            // owner dumps its column (= w = P[:,v]) to smem
            if (v & 32) {
                #pragma unroll
                for (int p = 0; p < 32; p += 2) {
                    ulonglong2 t2; t2.x = cB[p]; t2.y = cB[p + 1];
                    *reinterpret_cast<ulonglong2*>(sb + 2 * p) = t2;
                }
            } else {
                #pragma unroll
                for (int p = 0; p < 32; p += 2) {
                    ulonglong2 t2; t2.x = cA[p]; t2.y = cA[p + 1];
                    *reinterpret_cast<ulonglong2*>(sb + 2 * p) = t2;
                }
            }
            sb[v] -= sr[v];     // s = w - (g/a) e_v ;  dP[:,j] = Gn[v][j] * s
        }
        __syncwarp();

        unsigned long long cp1 = bcast2(c1);
        unsigned long long cp2 = bcast2(c2);
        const ulonglong2* s2 = reinterpret_cast<const ulonglong2*>(sb);
        #pragma unroll
        for (int p = 0; p < 16; p++) {
            ulonglong2 sv = s2[p];
            cA[2 * p]     = fma_f32x2(cp1, sv.x, cA[2 * p]);
            cA[2 * p + 1] = fma_f32x2(cp1, sv.y, cA[2 * p + 1]);
            cB[2 * p]     = fma_f32x2(cp2, sv.x, cB[2 * p]);
            cB[2 * p + 1] = fma_f32x2(cp2, sv.y, cB[2 * p + 1]);
        }
        v = vn; c1 = c1n; c2 = c2n;
    }

    // ---- final readout: logits = P[:,v_q]^T Z + bias2 ----
    int vq = seqb[LL - 1];
    float* sb = sbuf[w][1];     // step 1022 used buffer 0; buffer 1 is safe to overwrite
    if (lane == (vq & 31)) {
        if (vq & 32) {
            #pragma unroll
            for (int p = 0; p < 32; p += 2) {
                ulonglong2 t2; t2.x = cB[p]; t2.y = cB[p + 1];
                *reinterpret_cast<ulonglong2*>(sb + 2 * p) = t2;
            }
        } else {
            #pragma unroll
            for (int p = 0; p < 32; p += 2) {
                ulonglong2 t2; t2.x = cA[p]; t2.y = cA[p + 1];
                *reinterpret_cast<ulonglong2*>(sb + 2 * p) = t2;
            }
        }
    }
    __syncwarp();

    float acc1 = d_bias2[lane];
    float acc2 = d_bias2[lane + 32];
    #pragma unroll
    for (int i = 0; i < HH; i++) {
        float pi = sb[i];
        acc1 = fmaf(pi, d_Z[i * HH + lane], acc1);
        acc2 = fmaf(pi, d_Z[i * HH + 32 + lane], acc2);
    }
    out[(long)b * HH + lane]      = acc1;
    out[(long)b * HH + 32 + lane] = acc2;
}

// ---------------- launch ----------------
extern "C" void kernel_launch(void* const* d_in, const int* in_sizes, int n_in,
                              void* d_out, int out_size)
{
    const int*   seq     = (const int*)  d_in[0];
    const float* embed_W = (const float*)d_in[1];
    const float* ff_w1   = (const float*)d_in[2];
    const float* ff_b1   = (const float*)d_in[3];
    const float* ff_w2   = (const float*)d_in[4];
    const float* ff_b2   = (const float*)d_in[5];
    const float* ln_g    = (const float*)d_in[6];
    const float* ln_b    = (const float*)d_in[7];
    const float* gate_w1 = (const float*)d_in[8];
    const float* gate_b1 = (const float*)d_in[9];
    const float* gate_w2 = (const float*)d_in[10];
    const float* gate_b2 = (const float*)d_in[11];
    const float* read_w  = (const float*)d_in[12];
    const float* read_b  = (const float*)d_in[13];
    const float* out_w   = (const float*)d_in[14];
    const float* out_b   = (const float*)d_in[15];

    prekA<<<HH, 128>>>(embed_W, ff_w1, ff_b1, ff_w2, ff_b2, ln_g, ln_b,
                       gate_w1, gate_b1, gate_w2, gate_b2);
    prekB<<<HH, HH>>>(read_w, read_b, out_w, out_b);
    prekC<<<HH, HH>>>();
    scan_kernel<<<BB / 4, 128>>>(seq, (float*)d_out);
}